// round 15
// baseline (speedup 1.0000x reference)
#include <cuda_runtime.h>
#include <cuda_fp16.h>
#include <math.h>
#include <stdint.h>

#define D_MODEL 2048
#define N_HEADS 16
#define N_KV 4
#define HEAD_DIM 128
#define B_SZ 2
#define T_SEQ 2048
#define M_ROWS (B_SZ * T_SEQ)          // 4096
#define QDIM (N_HEADS * HEAD_DIM)      // 2048
#define KVDIM (N_KV * HEAD_DIM)        // 512
#define QKVD (QDIM + 2 * KVDIM)        // 3072

// ---------------- scratch ----------------
__device__ __half g_qkv[M_ROWS * QKVD];
__device__ __half g_att[M_ROWS * QDIM];
__device__ __half g_xh[M_ROWS * D_MODEL];
__device__ __half g_wc[(size_t)D_MODEL * QKVD];    // concat weights [k][n] fp16
__device__ __half g_wo[(size_t)QDIM * D_MODEL];    // Wo [k][n] fp16
__device__ float2 g_tab[T_SEQ * 64];               // rope cos/sin table

// ---------------- helpers ----------------
__device__ __forceinline__ uint32_t s2u(const void* p) {
    uint32_t a;
    asm("{ .reg .u64 t; cvta.to.shared.u64 t, %1; cvt.u32.u64 %0, t; }" : "=r"(a) : "l"(p));
    return a;
}
__device__ __forceinline__ void cpa16(uint32_t dst, const void* src) {
    asm volatile("cp.async.cg.shared.global [%0], [%1], 16;" :: "r"(dst), "l"(src));
}
__device__ __forceinline__ void cpa_commit() { asm volatile("cp.async.commit_group;" ::: "memory"); }
template <int N> __device__ __forceinline__ void cpa_wait() {
    asm volatile("cp.async.wait_group %0;" :: "n"(N) : "memory");
}
__device__ __forceinline__ void ldsm4(uint32_t& r0, uint32_t& r1, uint32_t& r2, uint32_t& r3,
                                      uint32_t addr) {
    asm volatile("ldmatrix.sync.aligned.m8n8.x4.shared.b16 {%0,%1,%2,%3}, [%4];"
                 : "=r"(r0), "=r"(r1), "=r"(r2), "=r"(r3) : "r"(addr));
}
__device__ __forceinline__ void ldsm4t(uint32_t& r0, uint32_t& r1, uint32_t& r2, uint32_t& r3,
                                       uint32_t addr) {
    asm volatile("ldmatrix.sync.aligned.m8n8.x4.trans.shared.b16 {%0,%1,%2,%3}, [%4];"
                 : "=r"(r0), "=r"(r1), "=r"(r2), "=r"(r3) : "r"(addr));
}
__device__ __forceinline__ void mma16(float* c, uint32_t a0, uint32_t a1, uint32_t a2, uint32_t a3,
                                      uint32_t b0, uint32_t b1) {
    asm volatile(
        "mma.sync.aligned.m16n8k16.row.col.f32.f16.f16.f32 "
        "{%0,%1,%2,%3},{%4,%5,%6,%7},{%8,%9},{%0,%1,%2,%3};"
        : "+f"(c[0]), "+f"(c[1]), "+f"(c[2]), "+f"(c[3])
        : "r"(a0), "r"(a1), "r"(a2), "r"(a3), "r"(b0), "r"(b1));
}
__device__ __forceinline__ uint32_t ex2h2(float a, float b) {
    __half2 h = __floats2half2_rn(a, b);
    uint32_t r;
    asm("ex2.approx.f16x2 %0, %1;" : "=r"(r) : "r"(*(uint32_t*)&h));
    return r;
}

// ---------------- GEMM: 128x128 CTA tile, 4 warps x 64x64 warp tile ----------------
#define GBM 128
#define GBN 128
#define GBK 64
#define ASTH 72
#define BSTH 136
#define ASTGH (128 * ASTH)
#define BSTGH (64 * BSTH)
#define GTHREADS 128

template <typename TO, bool ROPE>
__global__ __launch_bounds__(GTHREADS, 2) void gemm_h(const __half* __restrict__ A,
                                                      const __half* __restrict__ B,
                                                      TO* __restrict__ C,
                                                      int M, int N, int K) {
    extern __shared__ __half smh[];
    const uint32_t asb = s2u(smh);
    const uint32_t bsb = asb + 3 * ASTGH * 2;

    const int tid = threadIdx.x;
    const int lane = tid & 31, warp = tid >> 5;
    const int wm = warp >> 1, wn = warp & 1;    // 2 x 2 warps, warp tile 64x64
    const int g = lane >> 2, tg = lane & 3;
    const int bm = blockIdx.y * GBM, bn = blockIdx.x * GBN;
    const int NK = K / GBK;

    uint32_t aoff[4];
#pragma unroll
    for (int mt = 0; mt < 4; mt++)
        aoff[mt] = (uint32_t)(((wm * 64 + mt * 16 + (lane & 15)) * ASTH + ((lane >> 4) << 3)) * 2);
    const uint32_t b_lo = (uint32_t)(((((lane >> 3) & 1) * 8 + (lane & 7)) * BSTH +
                                      ((lane >> 4) << 3)) * 2);

    float acc[4][8][4];
#pragma unroll
    for (int mt = 0; mt < 4; mt++)
#pragma unroll
        for (int nt = 0; nt < 8; nt++)
#pragma unroll
            for (int r = 0; r < 4; r++) acc[mt][nt][r] = 0.f;

    auto fill = [&](int kt) {
        const int s = kt - (kt / 3) * 3;
        const int k0 = kt * GBK;
#pragma unroll
        for (int i = 0; i < 8; i++) {           // A: 128 rows x 8 chunks
            int ch = tid + i * GTHREADS;
            int r = ch >> 3, j = ch & 7;
            cpa16(asb + (uint32_t)((s * ASTGH + r * ASTH) * 2 + j * 16),
                  A + (size_t)(bm + r) * K + k0 + 8 * j);
        }
#pragma unroll
        for (int i = 0; i < 8; i++) {           // B: 64 k-rows x 16 chunks
            int ch = tid + i * GTHREADS;
            int r = ch >> 4, j = ch & 15;
            cpa16(bsb + (uint32_t)((s * BSTGH + r * BSTH) * 2 + j * 16),
                  B + (size_t)(k0 + r) * N + bn + 8 * j);
        }
    };

    fill(0); cpa_commit();
    fill(1); cpa_commit();

    for (int kt = 0; kt < NK; kt++) {
        cpa_wait<1>();
        __syncthreads();
        if (kt + 2 < NK) fill(kt + 2);
        cpa_commit();

        const int s = kt - (kt / 3) * 3;
        const uint32_t ab = asb + (uint32_t)(s * ASTGH * 2);
        const uint32_t bb = bsb + (uint32_t)(s * BSTGH * 2);
#pragma unroll
        for (int ks = 0; ks < 4; ks++) {
            uint32_t af[4][4], bf[8][2];
#pragma unroll
            for (int mt = 0; mt < 4; mt++)
                ldsm4(af[mt][0], af[mt][1], af[mt][2], af[mt][3], ab + aoff[mt] + ks * 32);
            const uint32_t bslab = bb + b_lo + (uint32_t)(ks * 16 * BSTH * 2);
#pragma unroll
            for (int nl = 0; nl < 4; nl++) {
                int ntp = wn * 4 + nl;          // 16-col group within the 128-col tile
                ldsm4t(bf[2 * nl][0], bf[2 * nl][1], bf[2 * nl + 1][0], bf[2 * nl + 1][1],
                       bslab + ntp * 32);
            }
#pragma unroll
            for (int mt = 0; mt < 4; mt++)
#pragma unroll
                for (int nt = 0; nt < 8; nt++)
                    mma16(acc[mt][nt], af[mt][0], af[mt][1], af[mt][2], af[mt][3], bf[nt][0], bf[nt][1]);
        }
    }

    if constexpr (ROPE) {
        cpa_wait<0>();
        __syncthreads();
        __half* Cs = smh;                       // 128 x 136
#pragma unroll
        for (int mt = 0; mt < 4; mt++)
#pragma unroll
            for (int nt = 0; nt < 8; nt++) {
                int r = wm * 64 + mt * 16 + g;
                int c = wn * 64 + nt * 8 + 2 * tg;
                *(__half2*)&Cs[r * 136 + c] = __floats2half2_rn(acc[mt][nt][0], acc[mt][nt][1]);
                *(__half2*)&Cs[(r + 8) * 136 + c] = __floats2half2_rn(acc[mt][nt][2], acc[mt][nt][3]);
            }
        __syncthreads();
        if (bn < 2560) {                        // q/k panels: rotate column pairs (i, i+64)
            for (int it = tid; it < 128 * 32; it += GTHREADS) {
                int r = it >> 5;
                int i2 = (it & 31) * 2;
                int t = (bm + r) & (T_SEQ - 1);
                float2 cs0 = g_tab[t * 64 + i2];
                float2 cs1 = g_tab[t * 64 + i2 + 1];
                float2 f1 = __half22float2(*(__half2*)&Cs[r * 136 + i2]);
                float2 f2 = __half22float2(*(__half2*)&Cs[r * 136 + 64 + i2]);
                *(__half2*)&C[(size_t)(bm + r) * N + bn + i2] =
                    __floats2half2_rn(f1.x * cs0.x - f2.x * cs0.y, f1.y * cs1.x - f2.y * cs1.y);
                *(__half2*)&C[(size_t)(bm + r) * N + bn + 64 + i2] =
                    __floats2half2_rn(f2.x * cs0.x + f1.x * cs0.y, f2.y * cs1.x + f1.y * cs1.y);
            }
        } else {                                // v panel: plain copy
            for (int it = tid; it < 128 * 64; it += GTHREADS) {
                int r = it >> 6;
                int c2 = (it & 63) * 2;
                *(__half2*)&C[(size_t)(bm + r) * N + bn + c2] = *(__half2*)&Cs[r * 136 + c2];
            }
        }
    } else {
#pragma unroll
        for (int mt = 0; mt < 4; mt++)
#pragma unroll
            for (int nt = 0; nt < 8; nt++) {
                int r = bm + wm * 64 + mt * 16 + g;
                int c = bn + wn * 64 + nt * 8 + 2 * tg;
                if constexpr (sizeof(TO) == 2) {
                    *(__half2*)&C[(size_t)r * N + c] =
                        __floats2half2_rn(acc[mt][nt][0], acc[mt][nt][1]);
                    *(__half2*)&C[(size_t)(r + 8) * N + c] =
                        __floats2half2_rn(acc[mt][nt][2], acc[mt][nt][3]);
                } else {
                    *(float2*)&C[(size_t)r * N + c] = make_float2(acc[mt][nt][0], acc[mt][nt][1]);
                    *(float2*)&C[(size_t)(r + 8) * N + c] = make_float2(acc[mt][nt][2], acc[mt][nt][3]);
                }
            }
    }
}

// ---------------- fused prep ----------------
__global__ void prep_all(const float* __restrict__ x, const float* __restrict__ Wq,
                         const float* __restrict__ Wk, const float* __restrict__ Wv,
                         const float* __restrict__ Wo, __half* __restrict__ xh,
                         __half* __restrict__ wc, __half* __restrict__ wo) {
    int bid = blockIdx.x;
    int tid = threadIdx.x;
    if (bid < 8192) {
        int i = bid * 256 + tid;
        float4 v = ((const float4*)x)[i];
        __half2 lo = __floats2half2_rn(v.x, v.y);
        __half2 hi = __floats2half2_rn(v.z, v.w);
        *(uint2*)&xh[i * 4] = make_uint2(*(uint32_t*)&lo, *(uint32_t*)&hi);
    } else if (bid < 14336) {
        int idx = (bid - 8192) * 256 + tid;
        const int n4row = QKVD / 4;
        int k = idx / n4row;
        int n = (idx - k * n4row) * 4;
        const float* src;
        int c;
        if (n < QDIM)      { src = Wq + (size_t)k * QDIM;  c = n; }
        else if (n < 2560) { src = Wk + (size_t)k * KVDIM; c = n - QDIM; }
        else               { src = Wv + (size_t)k * KVDIM; c = n - 2560; }
        float4 v = *(const float4*)(src + c);
        __half2 lo = __floats2half2_rn(v.x, v.y);
        __half2 hi = __floats2half2_rn(v.z, v.w);
        *(uint2*)&wc[(size_t)k * QKVD + n] = make_uint2(*(uint32_t*)&lo, *(uint32_t*)&hi);
    } else if (bid < 18432) {
        int i = (bid - 14336) * 256 + tid;
        float4 v = ((const float4*)Wo)[i];
        __half2 lo = __floats2half2_rn(v.x, v.y);
        __half2 hi = __floats2half2_rn(v.z, v.w);
        *(uint2*)&wo[i * 4] = make_uint2(*(uint32_t*)&lo, *(uint32_t*)&hi);
    } else {
        int gid = (bid - 18432) * 256 + tid;
        int i = gid & 63;
        int tt = gid >> 6;
        float inv = powf(10000.0f, -((float)(2 * i)) / 128.0f);
        float ang = (float)tt * inv;
        float s, c;
        sincosf(ang, &s, &c);
        g_tab[gid] = make_float2(c, s);
    }
}

// ---------------- flash attention: 4 warps x 32 rows, Bc=64, K+V double buffered ----------------
#define BQ 128
#define BKV 64
#define QSTH 136
#define KSTH 136
#define VSTH 136
#define KBUFH (BKV * KSTH)
#define VBUFH (BKV * VSTH)
#define ATHREADS 128

__global__ __launch_bounds__(ATHREADS, 2) void attn_h(const __half* __restrict__ QKV,
                                                      __half* __restrict__ O) {
    extern __shared__ __half smh[];
    __half* Qs = smh;
    __half* Ks = Qs + BQ * QSTH;
    __half* Vs = Ks + 2 * KBUFH;
    const uint32_t qsb = s2u(Qs), ksb = s2u(Ks), vsb = s2u(Vs);

    const int qt = (T_SEQ / BQ - 1) - blockIdx.x;
    const int h = blockIdx.y, b = blockIdx.z;
    const int kvh = h >> 2;
    const int tid = threadIdx.x, lane = tid & 31, warp = tid >> 5;
    const int g = lane >> 2, tg = lane & 3;
    const int wr0 = warp * 32;
    const int qrow0 = b * T_SEQ + qt * BQ;
    const float scale = 0.08838834764831845f;
    const float c2 = scale * 1.4426950408889634f;

    const __half* Qg = QKV + (size_t)h * 128;
    const __half* Kg = QKV + QDIM + (size_t)kvh * 128;
    const __half* Vg = QKV + 2560 + (size_t)kvh * 128;

    uint32_t q_lo[2];
#pragma unroll
    for (int mt = 0; mt < 2; mt++)
        q_lo[mt] = (uint32_t)(((wr0 + mt * 16 + (lane & 15)) * QSTH + ((lane >> 4) << 3)) * 2);
    const uint32_t k_lo = (uint32_t)((((lane & 7) + ((lane >> 4) << 3)) * KSTH +
                                      (((lane >> 3) & 1) << 3)) * 2);
    const uint32_t v_lo = (uint32_t)(((((lane >> 3) & 1) * 8 + (lane & 7)) * VSTH +
                                      ((lane >> 4) << 3)) * 2);

    auto fill_kv = [&](int kt) {
        const int s = kt & 1;
        const int kr0 = b * T_SEQ + kt * BKV;
#pragma unroll
        for (int i = 0; i < 8; i++) {
            int ch = tid + i * ATHREADS;
            int r = ch >> 4, j = ch & 15;
            cpa16(ksb + (uint32_t)((s * KBUFH + r * KSTH) * 2 + j * 16),
                  Kg + (size_t)(kr0 + r) * QKVD + 8 * j);
            cpa16(vsb + (uint32_t)((s * VBUFH + r * VSTH) * 2 + j * 16),
                  Vg + (size_t)(kr0 + r) * QKVD + 8 * j);
        }
    };

#pragma unroll
    for (int i = 0; i < 16; i++) {
        int ch = tid + i * ATHREADS;
        int r = ch >> 4, j = ch & 15;
        cpa16(qsb + (uint32_t)((r * QSTH) * 2 + j * 16), Qg + (size_t)(qrow0 + r) * QKVD + 8 * j);
    }
    fill_kv(0);
    cpa_commit();

    float m_[2][2], l_[2][2];
#pragma unroll
    for (int mt = 0; mt < 2; mt++) {
        m_[mt][0] = -INFINITY; m_[mt][1] = -INFINITY;
        l_[mt][0] = 0.f; l_[mt][1] = 0.f;
    }
    float o[2][16][4];
#pragma unroll
    for (int mt = 0; mt < 2; mt++)
#pragma unroll
        for (int nt = 0; nt < 16; nt++)
#pragma unroll
            for (int r = 0; r < 4; r++) o[mt][nt][r] = 0.f;

    const int kmax = 2 * qt + 1;
    for (int kt = 0; kt <= kmax; kt++) {
        cpa_wait<0>();
        __syncthreads();
        if (kt < kmax) { fill_kv(kt + 1); cpa_commit(); }

        const uint32_t kb = ksb + (uint32_t)((kt & 1) * KBUFH * 2);
        const uint32_t vb = vsb + (uint32_t)((kt & 1) * VBUFH * 2);

        float sc[2][8][4];
#pragma unroll
        for (int mt = 0; mt < 2; mt++)
#pragma unroll
            for (int nt = 0; nt < 8; nt++)
#pragma unroll
                for (int r = 0; r < 4; r++) sc[mt][nt][r] = 0.f;
#pragma unroll
        for (int kss = 0; kss < 8; kss++) {
            uint32_t a[2][4];
#pragma unroll
            for (int mt = 0; mt < 2; mt++)
                ldsm4(a[mt][0], a[mt][1], a[mt][2], a[mt][3], qsb + q_lo[mt] + kss * 32);
#pragma unroll
            for (int ntp = 0; ntp < 4; ntp++) {
                uint32_t b0, b1, b2, b3;
                ldsm4(b0, b1, b2, b3,
                      kb + k_lo + (uint32_t)(ntp * 16 * KSTH * 2) + kss * 32);
#pragma unroll
                for (int mt = 0; mt < 2; mt++) {
                    mma16(sc[mt][2 * ntp],     a[mt][0], a[mt][1], a[mt][2], a[mt][3], b0, b1);
                    mma16(sc[mt][2 * ntp + 1], a[mt][0], a[mt][1], a[mt][2], a[mt][3], b2, b3);
                }
            }
        }

        if (kt >= 2 * qt) {
#pragma unroll
            for (int mt = 0; mt < 2; mt++) {
                int lim_lo = qt * BQ + wr0 + mt * 16 + g - kt * BKV;
                int lim_hi = lim_lo + 8;
#pragma unroll
                for (int nt = 0; nt < 8; nt++) {
                    int cc = nt * 8 + 2 * tg;
                    if (cc     > lim_lo) sc[mt][nt][0] = -INFINITY;
                    if (cc + 1 > lim_lo) sc[mt][nt][1] = -INFINITY;
                    if (cc     > lim_hi) sc[mt][nt][2] = -INFINITY;
                    if (cc + 1 > lim_hi) sc[mt][nt][3] = -INFINITY;
                }
            }
        }

        uint32_t plo[2][8], phi[2][8];
        float al[2][2];
#pragma unroll
        for (int mt = 0; mt < 2; mt++) {
            float mx_lo = -INFINITY, mx_hi = -INFINITY;
#pragma unroll
            for (int nt = 0; nt < 8; nt++) {
                mx_lo = fmaxf(mx_lo, fmaxf(sc[mt][nt][0], sc[mt][nt][1]));
                mx_hi = fmaxf(mx_hi, fmaxf(sc[mt][nt][2], sc[mt][nt][3]));
            }
            mx_lo = fmaxf(mx_lo, __shfl_xor_sync(0xffffffffu, mx_lo, 1));
            mx_lo = fmaxf(mx_lo, __shfl_xor_sync(0xffffffffu, mx_lo, 2));
            mx_hi = fmaxf(mx_hi, __shfl_xor_sync(0xffffffffu, mx_hi, 1));
            mx_hi = fmaxf(mx_hi, __shfl_xor_sync(0xffffffffu, mx_hi, 2));

            float mn_lo = fmaxf(m_[mt][0], mx_lo), mn_hi = fmaxf(m_[mt][1], mx_hi);
            al[mt][0] = __expf((m_[mt][0] - mn_lo) * scale);
            al[mt][1] = __expf((m_[mt][1] - mn_hi) * scale);
            float ls_lo = 0.f, ls_hi = 0.f;
#pragma unroll
            for (int nt = 0; nt < 8; nt++) {
                plo[mt][nt] = ex2h2((sc[mt][nt][0] - mn_lo) * c2, (sc[mt][nt][1] - mn_lo) * c2);
                phi[mt][nt] = ex2h2((sc[mt][nt][2] - mn_hi) * c2, (sc[mt][nt][3] - mn_hi) * c2);
                float2 flo = __half22float2(*(__half2*)&plo[mt][nt]);
                float2 fhi = __half22float2(*(__half2*)&phi[mt][nt]);
                ls_lo += flo.x + flo.y;
                ls_hi += fhi.x + fhi.y;
            }
            ls_lo += __shfl_xor_sync(0xffffffffu, ls_lo, 1);
            ls_lo += __shfl_xor_sync(0xffffffffu, ls_lo, 2);
            ls_hi += __shfl_xor_sync(0xffffffffu, ls_hi, 1);
            ls_hi += __shfl_xor_sync(0xffffffffu, ls_hi, 2);
            l_[mt][0] = l_[mt][0] * al[mt][0] + ls_lo;
            l_[mt][1] = l_[mt][1] * al[mt][1] + ls_hi;
            m_[mt][0] = mn_lo; m_[mt][1] = mn_hi;
        }

#pragma unroll
        for (int mt = 0; mt < 2; mt++)
#pragma unroll
            for (int nt = 0; nt < 16; nt++) {
                o[mt][nt][0] *= al[mt][0]; o[mt][nt][1] *= al[mt][0];
                o[mt][nt][2] *= al[mt][1]; o[mt][nt][3] *= al[mt][1];
            }
#pragma unroll
        for (int kss = 0; kss < 4; kss++) {
            const uint32_t vslab = vb + v_lo + (uint32_t)(kss * 16 * VSTH * 2);
#pragma unroll
            for (int ntp = 0; ntp < 8; ntp++) {
                uint32_t b0, b1, b2, b3;
                ldsm4t(b0, b1, b2, b3, vslab + ntp * 32);
#pragma unroll
                for (int mt = 0; mt < 2; mt++) {
                    uint32_t a0 = plo[mt][2 * kss],     a1 = phi[mt][2 * kss];
                    uint32_t a2 = plo[mt][2 * kss + 1], a3 = phi[mt][2 * kss + 1];
                    mma16(o[mt][2 * ntp],     a0, a1, a2, a3, b0, b1);
                    mma16(o[mt][2 * ntp + 1], a0, a1, a2, a3, b2, b3);
                }
            }
        }
    }

#pragma unroll
    for (int mt = 0; mt < 2; mt++) {
        float li = 1.f / l_[mt][0], lh = 1.f / l_[mt][1];
#pragma unroll
        for (int nt = 0; nt < 16; nt++) {
            int c = h * HEAD_DIM + nt * 8 + 2 * tg;
            int r = qrow0 + wr0 + mt * 16 + g;
            *(__half2*)&O[(size_t)r * QDIM + c] =
                __floats2half2_rn(o[mt][nt][0] * li, o[mt][nt][1] * li);
            *(__half2*)&O[(size_t)(r + 8) * QDIM + c] =
                __floats2half2_rn(o[mt][nt][2] * lh, o[mt][nt][3] * lh);
        }
    }
}

// ---------------- launch ----------------
extern "C" void kernel_launch(void* const* d_in, const int* in_sizes, int n_in,
                              void* d_out, int out_size) {
    const float* x  = (const float*)d_in[0];
    const float* Wq = (const float*)d_in[1];
    const float* Wk = (const float*)d_in[2];
    const float* Wv = (const float*)d_in[3];
    const float* Wo = (const float*)d_in[4];
    float* out = (float*)d_out;

    __half *qkv, *att, *xh, *wc, *wo;
    cudaGetSymbolAddress((void**)&qkv, g_qkv);
    cudaGetSymbolAddress((void**)&att, g_att);
    cudaGetSymbolAddress((void**)&xh, g_xh);
    cudaGetSymbolAddress((void**)&wc, g_wc);
    cudaGetSymbolAddress((void**)&wo, g_wo);

    prep_all<<<18944, 256>>>(x, Wq, Wk, Wv, Wo, xh, wc, wo);

    const int GSM = 3 * (ASTGH + BSTGH) * 2;   // 107520
    cudaFuncSetAttribute((const void*)gemm_h<__half, true>,
                         cudaFuncAttributeMaxDynamicSharedMemorySize, GSM);
    cudaFuncSetAttribute((const void*)gemm_h<float, false>,
                         cudaFuncAttributeMaxDynamicSharedMemorySize, GSM);

    gemm_h<__half, true><<<dim3(QKVD / GBN, M_ROWS / GBM), GTHREADS, GSM>>>(xh, wc, qkv,
                                                                            M_ROWS, QKVD, D_MODEL);

    {
        const int ASM_ = (BQ * QSTH + 2 * KBUFH + 2 * VBUFH) * 2;   // 104448
        cudaFuncSetAttribute(attn_h, cudaFuncAttributeMaxDynamicSharedMemorySize, ASM_);
        attn_h<<<dim3(T_SEQ / BQ, N_HEADS, B_SZ), ATHREADS, ASM_>>>(qkv, att);
    }

    gemm_h<float, false><<<dim3(D_MODEL / GBN, M_ROWS / GBM), GTHREADS, GSM>>>(att, wo, out,
                                                                               M_ROWS, D_MODEL, QDIM);
}

// round 16
// speedup vs baseline: 1.0278x; 1.0278x over previous
#include <cuda_runtime.h>
#include <cuda_fp16.h>
#include <math.h>
#include <stdint.h>

#define D_MODEL 2048
#define N_HEADS 16
#define N_KV 4
#define HEAD_DIM 128
#define B_SZ 2
#define T_SEQ 2048
#define M_ROWS (B_SZ * T_SEQ)          // 4096
#define QDIM (N_HEADS * HEAD_DIM)      // 2048
#define KVDIM (N_KV * HEAD_DIM)        // 512
#define QKVD (QDIM + 2 * KVDIM)        // 3072

// ---------------- scratch ----------------
__device__ __half g_qkv[M_ROWS * QKVD];
__device__ __half g_att[M_ROWS * QDIM];
__device__ __half g_xh[M_ROWS * D_MODEL];
__device__ __half g_wc[(size_t)D_MODEL * QKVD];    // concat weights [k][n] fp16
__device__ __half g_wo[(size_t)QDIM * D_MODEL];    // Wo [k][n] fp16
__device__ float2 g_tab[T_SEQ * 64];               // rope cos/sin table

// ---------------- helpers ----------------
__device__ __forceinline__ uint32_t s2u(const void* p) {
    uint32_t a;
    asm("{ .reg .u64 t; cvta.to.shared.u64 t, %1; cvt.u32.u64 %0, t; }" : "=r"(a) : "l"(p));
    return a;
}
__device__ __forceinline__ void cpa16(uint32_t dst, const void* src) {
    asm volatile("cp.async.cg.shared.global [%0], [%1], 16;" :: "r"(dst), "l"(src));
}
__device__ __forceinline__ void cpa_commit() { asm volatile("cp.async.commit_group;" ::: "memory"); }
template <int N> __device__ __forceinline__ void cpa_wait() {
    asm volatile("cp.async.wait_group %0;" :: "n"(N) : "memory");
}
__device__ __forceinline__ void ldsm4(uint32_t& r0, uint32_t& r1, uint32_t& r2, uint32_t& r3,
                                      uint32_t addr) {
    asm volatile("ldmatrix.sync.aligned.m8n8.x4.shared.b16 {%0,%1,%2,%3}, [%4];"
                 : "=r"(r0), "=r"(r1), "=r"(r2), "=r"(r3) : "r"(addr));
}
__device__ __forceinline__ void ldsm4t(uint32_t& r0, uint32_t& r1, uint32_t& r2, uint32_t& r3,
                                       uint32_t addr) {
    asm volatile("ldmatrix.sync.aligned.m8n8.x4.trans.shared.b16 {%0,%1,%2,%3}, [%4];"
                 : "=r"(r0), "=r"(r1), "=r"(r2), "=r"(r3) : "r"(addr));
}
__device__ __forceinline__ void mma16(float* c, uint32_t a0, uint32_t a1, uint32_t a2, uint32_t a3,
                                      uint32_t b0, uint32_t b1) {
    asm volatile(
        "mma.sync.aligned.m16n8k16.row.col.f32.f16.f16.f32 "
        "{%0,%1,%2,%3},{%4,%5,%6,%7},{%8,%9},{%0,%1,%2,%3};"
        : "+f"(c[0]), "+f"(c[1]), "+f"(c[2]), "+f"(c[3])
        : "r"(a0), "r"(a1), "r"(a2), "r"(a3), "r"(b0), "r"(b1));
}
__device__ __forceinline__ uint32_t ex2h2(float a, float b) {
    __half2 h = __floats2half2_rn(a, b);
    uint32_t r;
    asm("ex2.approx.f16x2 %0, %1;" : "=r"(r) : "r"(*(uint32_t*)&h));
    return r;
}

// ---------------- shared GEMM tiling constants ----------------
#define GBM 128
#define GBN 128
#define GBK 64
#define ASTH 72
#define BSTH 136
#define ASTGH (128 * ASTH)
#define BSTGH (64 * BSTH)

// ---------------- QKV GEMM: 256 threads, 2x4 warps, 64x32 warp tile, ROPE epilogue ----------------
__global__ __launch_bounds__(256, 2) void gemm_qkv(const __half* __restrict__ A,
                                                   const __half* __restrict__ B,
                                                   __half* __restrict__ C,
                                                   int M, int N, int K) {
    extern __shared__ __half smh[];
    const uint32_t asb = s2u(smh);
    const uint32_t bsb = asb + 3 * ASTGH * 2;

    const int tid = threadIdx.x;
    const int lane = tid & 31, warp = tid >> 5;
    const int wm = warp >> 2, wn = warp & 3;    // 2 x 4 warps, warp tile 64x32
    const int g = lane >> 2, tg = lane & 3;
    const int bm = blockIdx.y * GBM, bn = blockIdx.x * GBN;
    const int NK = K / GBK;

    uint32_t aoff[4];
#pragma unroll
    for (int mt = 0; mt < 4; mt++)
        aoff[mt] = (uint32_t)(((wm * 64 + mt * 16 + (lane & 15)) * ASTH + ((lane >> 4) << 3)) * 2);
    const uint32_t b_lo = (uint32_t)(((((lane >> 3) & 1) * 8 + (lane & 7)) * BSTH +
                                      ((lane >> 4) << 3)) * 2);

    float acc[4][4][4];
#pragma unroll
    for (int mt = 0; mt < 4; mt++)
#pragma unroll
        for (int nt = 0; nt < 4; nt++)
#pragma unroll
            for (int r = 0; r < 4; r++) acc[mt][nt][r] = 0.f;

    auto fill = [&](int kt) {
        const int s = kt - (kt / 3) * 3;
        const int k0 = kt * GBK;
#pragma unroll
        for (int i = 0; i < 4; i++) {
            int ch = tid + i * 256;
            int r = ch >> 3, j = ch & 7;
            cpa16(asb + (uint32_t)((s * ASTGH + r * ASTH) * 2 + j * 16),
                  A + (size_t)(bm + r) * K + k0 + 8 * j);
        }
#pragma unroll
        for (int i = 0; i < 4; i++) {
            int ch = tid + i * 256;
            int r = ch >> 4, j = ch & 15;
            cpa16(bsb + (uint32_t)((s * BSTGH + r * BSTH) * 2 + j * 16),
                  B + (size_t)(k0 + r) * N + bn + 8 * j);
        }
    };

    fill(0); cpa_commit();
    fill(1); cpa_commit();

    for (int kt = 0; kt < NK; kt++) {
        cpa_wait<1>();
        __syncthreads();
        if (kt + 2 < NK) fill(kt + 2);
        cpa_commit();

        const int s = kt - (kt / 3) * 3;
        const uint32_t ab = asb + (uint32_t)(s * ASTGH * 2);
        const uint32_t bb = bsb + (uint32_t)(s * BSTGH * 2);
#pragma unroll
        for (int ks = 0; ks < 4; ks++) {
            uint32_t af[4][4], bf[4][2];
#pragma unroll
            for (int mt = 0; mt < 4; mt++)
                ldsm4(af[mt][0], af[mt][1], af[mt][2], af[mt][3], ab + aoff[mt] + ks * 32);
            const uint32_t bslab = bb + b_lo + (uint32_t)(ks * 16 * BSTH * 2);
#pragma unroll
            for (int nl = 0; nl < 2; nl++) {
                int ntp = wn * 2 + nl;
                ldsm4t(bf[2 * nl][0], bf[2 * nl][1], bf[2 * nl + 1][0], bf[2 * nl + 1][1],
                       bslab + ntp * 32);
            }
#pragma unroll
            for (int mt = 0; mt < 4; mt++)
#pragma unroll
                for (int nt = 0; nt < 4; nt++)
                    mma16(acc[mt][nt], af[mt][0], af[mt][1], af[mt][2], af[mt][3], bf[nt][0], bf[nt][1]);
        }
    }

    // ROPE epilogue: stage tile in smem, rotate (q/k) or copy (v)
    cpa_wait<0>();
    __syncthreads();
    __half* Cs = smh;                       // 128 x 136
#pragma unroll
    for (int mt = 0; mt < 4; mt++)
#pragma unroll
        for (int nt = 0; nt < 4; nt++) {
            int r = wm * 64 + mt * 16 + g;
            int c = wn * 32 + nt * 8 + 2 * tg;
            *(__half2*)&Cs[r * 136 + c] = __floats2half2_rn(acc[mt][nt][0], acc[mt][nt][1]);
            *(__half2*)&Cs[(r + 8) * 136 + c] = __floats2half2_rn(acc[mt][nt][2], acc[mt][nt][3]);
        }
    __syncthreads();
    if (bn < 2560) {
        for (int it = tid; it < 128 * 32; it += 256) {
            int r = it >> 5;
            int i2 = (it & 31) * 2;
            int t = (bm + r) & (T_SEQ - 1);
            float2 cs0 = g_tab[t * 64 + i2];
            float2 cs1 = g_tab[t * 64 + i2 + 1];
            float2 f1 = __half22float2(*(__half2*)&Cs[r * 136 + i2]);
            float2 f2 = __half22float2(*(__half2*)&Cs[r * 136 + 64 + i2]);
            *(__half2*)&C[(size_t)(bm + r) * N + bn + i2] =
                __floats2half2_rn(f1.x * cs0.x - f2.x * cs0.y, f1.y * cs1.x - f2.y * cs1.y);
            *(__half2*)&C[(size_t)(bm + r) * N + bn + 64 + i2] =
                __floats2half2_rn(f2.x * cs0.x + f1.x * cs0.y, f2.y * cs1.x + f1.y * cs1.y);
        }
    } else {
        for (int it = tid; it < 128 * 64; it += 256) {
            int r = it >> 6;
            int c2 = (it & 63) * 2;
            *(__half2*)&C[(size_t)(bm + r) * N + bn + c2] = *(__half2*)&Cs[r * 136 + c2];
        }
    }
}

// ---------------- out-proj GEMM: 128 threads, 2x2 warps, 64x64 warp tile ----------------
__global__ __launch_bounds__(128, 2) void gemm_out(const __half* __restrict__ A,
                                                   const __half* __restrict__ B,
                                                   float* __restrict__ C,
                                                   int M, int N, int K) {
    extern __shared__ __half smh[];
    const uint32_t asb = s2u(smh);
    const uint32_t bsb = asb + 3 * ASTGH * 2;

    const int tid = threadIdx.x;
    const int lane = tid & 31, warp = tid >> 5;
    const int wm = warp >> 1, wn = warp & 1;    // 2 x 2 warps, warp tile 64x64
    const int g = lane >> 2, tg = lane & 3;
    const int bm = blockIdx.y * GBM, bn = blockIdx.x * GBN;
    const int NK = K / GBK;

    uint32_t aoff[4];
#pragma unroll
    for (int mt = 0; mt < 4; mt++)
        aoff[mt] = (uint32_t)(((wm * 64 + mt * 16 + (lane & 15)) * ASTH + ((lane >> 4) << 3)) * 2);
    const uint32_t b_lo = (uint32_t)(((((lane >> 3) & 1) * 8 + (lane & 7)) * BSTH +
                                      ((lane >> 4) << 3)) * 2);

    float acc[4][8][4];
#pragma unroll
    for (int mt = 0; mt < 4; mt++)
#pragma unroll
        for (int nt = 0; nt < 8; nt++)
#pragma unroll
            for (int r = 0; r < 4; r++) acc[mt][nt][r] = 0.f;

    auto fill = [&](int kt) {
        const int s = kt - (kt / 3) * 3;
        const int k0 = kt * GBK;
#pragma unroll
        for (int i = 0; i < 8; i++) {
            int ch = tid + i * 128;
            int r = ch >> 3, j = ch & 7;
            cpa16(asb + (uint32_t)((s * ASTGH + r * ASTH) * 2 + j * 16),
                  A + (size_t)(bm + r) * K + k0 + 8 * j);
        }
#pragma unroll
        for (int i = 0; i < 8; i++) {
            int ch = tid + i * 128;
            int r = ch >> 4, j = ch & 15;
            cpa16(bsb + (uint32_t)((s * BSTGH + r * BSTH) * 2 + j * 16),
                  B + (size_t)(k0 + r) * N + bn + 8 * j);
        }
    };

    fill(0); cpa_commit();
    fill(1); cpa_commit();

    for (int kt = 0; kt < NK; kt++) {
        cpa_wait<1>();
        __syncthreads();
        if (kt + 2 < NK) fill(kt + 2);
        cpa_commit();

        const int s = kt - (kt / 3) * 3;
        const uint32_t ab = asb + (uint32_t)(s * ASTGH * 2);
        const uint32_t bb = bsb + (uint32_t)(s * BSTGH * 2);
#pragma unroll
        for (int ks = 0; ks < 4; ks++) {
            uint32_t af[4][4], bf[8][2];
#pragma unroll
            for (int mt = 0; mt < 4; mt++)
                ldsm4(af[mt][0], af[mt][1], af[mt][2], af[mt][3], ab + aoff[mt] + ks * 32);
            const uint32_t bslab = bb + b_lo + (uint32_t)(ks * 16 * BSTH * 2);
#pragma unroll
            for (int nl = 0; nl < 4; nl++) {
                int ntp = wn * 4 + nl;
                ldsm4t(bf[2 * nl][0], bf[2 * nl][1], bf[2 * nl + 1][0], bf[2 * nl + 1][1],
                       bslab + ntp * 32);
            }
#pragma unroll
            for (int mt = 0; mt < 4; mt++)
#pragma unroll
                for (int nt = 0; nt < 8; nt++)
                    mma16(acc[mt][nt], af[mt][0], af[mt][1], af[mt][2], af[mt][3], bf[nt][0], bf[nt][1]);
        }
    }

#pragma unroll
    for (int mt = 0; mt < 4; mt++)
#pragma unroll
        for (int nt = 0; nt < 8; nt++) {
            int r = bm + wm * 64 + mt * 16 + g;
            int c = bn + wn * 64 + nt * 8 + 2 * tg;
            *(float2*)&C[(size_t)r * N + c] = make_float2(acc[mt][nt][0], acc[mt][nt][1]);
            *(float2*)&C[(size_t)(r + 8) * N + c] = make_float2(acc[mt][nt][2], acc[mt][nt][3]);
        }
}

// ---------------- fused prep ----------------
__global__ void prep_all(const float* __restrict__ x, const float* __restrict__ Wq,
                         const float* __restrict__ Wk, const float* __restrict__ Wv,
                         const float* __restrict__ Wo, __half* __restrict__ xh,
                         __half* __restrict__ wc, __half* __restrict__ wo) {
    int bid = blockIdx.x;
    int tid = threadIdx.x;
    if (bid < 8192) {
        int i = bid * 256 + tid;
        float4 v = ((const float4*)x)[i];
        __half2 lo = __floats2half2_rn(v.x, v.y);
        __half2 hi = __floats2half2_rn(v.z, v.w);
        *(uint2*)&xh[i * 4] = make_uint2(*(uint32_t*)&lo, *(uint32_t*)&hi);
    } else if (bid < 14336) {
        int idx = (bid - 8192) * 256 + tid;
        const int n4row = QKVD / 4;
        int k = idx / n4row;
        int n = (idx - k * n4row) * 4;
        const float* src;
        int c;
        if (n < QDIM)      { src = Wq + (size_t)k * QDIM;  c = n; }
        else if (n < 2560) { src = Wk + (size_t)k * KVDIM; c = n - QDIM; }
        else               { src = Wv + (size_t)k * KVDIM; c = n - 2560; }
        float4 v = *(const float4*)(src + c);
        __half2 lo = __floats2half2_rn(v.x, v.y);
        __half2 hi = __floats2half2_rn(v.z, v.w);
        *(uint2*)&wc[(size_t)k * QKVD + n] = make_uint2(*(uint32_t*)&lo, *(uint32_t*)&hi);
    } else if (bid < 18432) {
        int i = (bid - 14336) * 256 + tid;
        float4 v = ((const float4*)Wo)[i];
        __half2 lo = __floats2half2_rn(v.x, v.y);
        __half2 hi = __floats2half2_rn(v.z, v.w);
        *(uint2*)&wo[i * 4] = make_uint2(*(uint32_t*)&lo, *(uint32_t*)&hi);
    } else {
        int gid = (bid - 18432) * 256 + tid;
        int i = gid & 63;
        int tt = gid >> 6;
        float inv = powf(10000.0f, -((float)(2 * i)) / 128.0f);
        float ang = (float)tt * inv;
        float s, c;
        sincosf(ang, &s, &c);
        g_tab[gid] = make_float2(c, s);
    }
}

// ---------------- flash attention: 4 warps x 32 rows, Bc=64, K+V double buffered ----------------
#define BQ 128
#define BKV 64
#define QSTH 136
#define KSTH 136
#define VSTH 136
#define KBUFH (BKV * KSTH)
#define VBUFH (BKV * VSTH)
#define ATHREADS 128

__global__ __launch_bounds__(ATHREADS, 2) void attn_h(const __half* __restrict__ QKV,
                                                      __half* __restrict__ O) {
    extern __shared__ __half smh[];
    __half* Qs = smh;
    __half* Ks = Qs + BQ * QSTH;
    __half* Vs = Ks + 2 * KBUFH;
    const uint32_t qsb = s2u(Qs), ksb = s2u(Ks), vsb = s2u(Vs);

    const int qt = (T_SEQ / BQ - 1) - blockIdx.x;
    const int h = blockIdx.y, b = blockIdx.z;
    const int kvh = h >> 2;
    const int tid = threadIdx.x, lane = tid & 31, warp = tid >> 5;
    const int g = lane >> 2, tg = lane & 3;
    const int wr0 = warp * 32;
    const int qrow0 = b * T_SEQ + qt * BQ;
    const float scale = 0.08838834764831845f;
    const float c2 = scale * 1.4426950408889634f;

    const __half* Qg = QKV + (size_t)h * 128;
    const __half* Kg = QKV + QDIM + (size_t)kvh * 128;
    const __half* Vg = QKV + 2560 + (size_t)kvh * 128;

    uint32_t q_lo[2];
#pragma unroll
    for (int mt = 0; mt < 2; mt++)
        q_lo[mt] = (uint32_t)(((wr0 + mt * 16 + (lane & 15)) * QSTH + ((lane >> 4) << 3)) * 2);
    const uint32_t k_lo = (uint32_t)((((lane & 7) + ((lane >> 4) << 3)) * KSTH +
                                      (((lane >> 3) & 1) << 3)) * 2);
    const uint32_t v_lo = (uint32_t)(((((lane >> 3) & 1) * 8 + (lane & 7)) * VSTH +
                                      ((lane >> 4) << 3)) * 2);

    auto fill_kv = [&](int kt) {
        const int s = kt & 1;
        const int kr0 = b * T_SEQ + kt * BKV;
#pragma unroll
        for (int i = 0; i < 8; i++) {
            int ch = tid + i * ATHREADS;
            int r = ch >> 4, j = ch & 15;
            cpa16(ksb + (uint32_t)((s * KBUFH + r * KSTH) * 2 + j * 16),
                  Kg + (size_t)(kr0 + r) * QKVD + 8 * j);
            cpa16(vsb + (uint32_t)((s * VBUFH + r * VSTH) * 2 + j * 16),
                  Vg + (size_t)(kr0 + r) * QKVD + 8 * j);
        }
    };

#pragma unroll
    for (int i = 0; i < 16; i++) {
        int ch = tid + i * ATHREADS;
        int r = ch >> 4, j = ch & 15;
        cpa16(qsb + (uint32_t)((r * QSTH) * 2 + j * 16), Qg + (size_t)(qrow0 + r) * QKVD + 8 * j);
    }
    fill_kv(0);
    cpa_commit();

    float m_[2][2], l_[2][2];
#pragma unroll
    for (int mt = 0; mt < 2; mt++) {
        m_[mt][0] = -INFINITY; m_[mt][1] = -INFINITY;
        l_[mt][0] = 0.f; l_[mt][1] = 0.f;
    }
    float o[2][16][4];
#pragma unroll
    for (int mt = 0; mt < 2; mt++)
#pragma unroll
        for (int nt = 0; nt < 16; nt++)
#pragma unroll
            for (int r = 0; r < 4; r++) o[mt][nt][r] = 0.f;

    const int kmax = 2 * qt + 1;
    for (int kt = 0; kt <= kmax; kt++) {
        cpa_wait<0>();
        __syncthreads();
        if (kt < kmax) { fill_kv(kt + 1); cpa_commit(); }

        const uint32_t kb = ksb + (uint32_t)((kt & 1) * KBUFH * 2);
        const uint32_t vb = vsb + (uint32_t)((kt & 1) * VBUFH * 2);

        float sc[2][8][4];
#pragma unroll
        for (int mt = 0; mt < 2; mt++)
#pragma unroll
            for (int nt = 0; nt < 8; nt++)
#pragma unroll
                for (int r = 0; r < 4; r++) sc[mt][nt][r] = 0.f;
#pragma unroll
        for (int kss = 0; kss < 8; kss++) {
            uint32_t a[2][4];
#pragma unroll
            for (int mt = 0; mt < 2; mt++)
                ldsm4(a[mt][0], a[mt][1], a[mt][2], a[mt][3], qsb + q_lo[mt] + kss * 32);
#pragma unroll
            for (int ntp = 0; ntp < 4; ntp++) {
                uint32_t b0, b1, b2, b3;
                ldsm4(b0, b1, b2, b3,
                      kb + k_lo + (uint32_t)(ntp * 16 * KSTH * 2) + kss * 32);
#pragma unroll
                for (int mt = 0; mt < 2; mt++) {
                    mma16(sc[mt][2 * ntp],     a[mt][0], a[mt][1], a[mt][2], a[mt][3], b0, b1);
                    mma16(sc[mt][2 * ntp + 1], a[mt][0], a[mt][1], a[mt][2], a[mt][3], b2, b3);
                }
            }
        }

        if (kt >= 2 * qt) {
#pragma unroll
            for (int mt = 0; mt < 2; mt++) {
                int lim_lo = qt * BQ + wr0 + mt * 16 + g - kt * BKV;
                int lim_hi = lim_lo + 8;
#pragma unroll
                for (int nt = 0; nt < 8; nt++) {
                    int cc = nt * 8 + 2 * tg;
                    if (cc     > lim_lo) sc[mt][nt][0] = -INFINITY;
                    if (cc + 1 > lim_lo) sc[mt][nt][1] = -INFINITY;
                    if (cc     > lim_hi) sc[mt][nt][2] = -INFINITY;
                    if (cc + 1 > lim_hi) sc[mt][nt][3] = -INFINITY;
                }
            }
        }

        uint32_t plo[2][8], phi[2][8];
        float al[2][2];
#pragma unroll
        for (int mt = 0; mt < 2; mt++) {
            float mx_lo = -INFINITY, mx_hi = -INFINITY;
#pragma unroll
            for (int nt = 0; nt < 8; nt++) {
                mx_lo = fmaxf(mx_lo, fmaxf(sc[mt][nt][0], sc[mt][nt][1]));
                mx_hi = fmaxf(mx_hi, fmaxf(sc[mt][nt][2], sc[mt][nt][3]));
            }
            mx_lo = fmaxf(mx_lo, __shfl_xor_sync(0xffffffffu, mx_lo, 1));
            mx_lo = fmaxf(mx_lo, __shfl_xor_sync(0xffffffffu, mx_lo, 2));
            mx_hi = fmaxf(mx_hi, __shfl_xor_sync(0xffffffffu, mx_hi, 1));
            mx_hi = fmaxf(mx_hi, __shfl_xor_sync(0xffffffffu, mx_hi, 2));

            float mn_lo = fmaxf(m_[mt][0], mx_lo), mn_hi = fmaxf(m_[mt][1], mx_hi);
            al[mt][0] = __expf((m_[mt][0] - mn_lo) * scale);
            al[mt][1] = __expf((m_[mt][1] - mn_hi) * scale);
            float ls_lo = 0.f, ls_hi = 0.f;
#pragma unroll
            for (int nt = 0; nt < 8; nt++) {
                plo[mt][nt] = ex2h2((sc[mt][nt][0] - mn_lo) * c2, (sc[mt][nt][1] - mn_lo) * c2);
                phi[mt][nt] = ex2h2((sc[mt][nt][2] - mn_hi) * c2, (sc[mt][nt][3] - mn_hi) * c2);
                float2 flo = __half22float2(*(__half2*)&plo[mt][nt]);
                float2 fhi = __half22float2(*(__half2*)&phi[mt][nt]);
                ls_lo += flo.x + flo.y;
                ls_hi += fhi.x + fhi.y;
            }
            ls_lo += __shfl_xor_sync(0xffffffffu, ls_lo, 1);
            ls_lo += __shfl_xor_sync(0xffffffffu, ls_lo, 2);
            ls_hi += __shfl_xor_sync(0xffffffffu, ls_hi, 1);
            ls_hi += __shfl_xor_sync(0xffffffffu, ls_hi, 2);
            l_[mt][0] = l_[mt][0] * al[mt][0] + ls_lo;
            l_[mt][1] = l_[mt][1] * al[mt][1] + ls_hi;
            m_[mt][0] = mn_lo; m_[mt][1] = mn_hi;
        }

#pragma unroll
        for (int mt = 0; mt < 2; mt++)
#pragma unroll
            for (int nt = 0; nt < 16; nt++) {
                o[mt][nt][0] *= al[mt][0]; o[mt][nt][1] *= al[mt][0];
                o[mt][nt][2] *= al[mt][1]; o[mt][nt][3] *= al[mt][1];
            }
#pragma unroll
        for (int kss = 0; kss < 4; kss++) {
            const uint32_t vslab = vb + v_lo + (uint32_t)(kss * 16 * VSTH * 2);
#pragma unroll
            for (int ntp = 0; ntp < 8; ntp++) {
                uint32_t b0, b1, b2, b3;
                ldsm4t(b0, b1, b2, b3, vslab + ntp * 32);
#pragma unroll
                for (int mt = 0; mt < 2; mt++) {
                    uint32_t a0 = plo[mt][2 * kss],     a1 = phi[mt][2 * kss];
                    uint32_t a2 = plo[mt][2 * kss + 1], a3 = phi[mt][2 * kss + 1];
                    mma16(o[mt][2 * ntp],     a0, a1, a2, a3, b0, b1);
                    mma16(o[mt][2 * ntp + 1], a0, a1, a2, a3, b2, b3);
                }
            }
        }
    }

#pragma unroll
    for (int mt = 0; mt < 2; mt++) {
        float li = 1.f / l_[mt][0], lh = 1.f / l_[mt][1];
#pragma unroll
        for (int nt = 0; nt < 16; nt++) {
            int c = h * HEAD_DIM + nt * 8 + 2 * tg;
            int r = qrow0 + wr0 + mt * 16 + g;
            *(__half2*)&O[(size_t)r * QDIM + c] =
                __floats2half2_rn(o[mt][nt][0] * li, o[mt][nt][1] * li);
            *(__half2*)&O[(size_t)(r + 8) * QDIM + c] =
                __floats2half2_rn(o[mt][nt][2] * lh, o[mt][nt][3] * lh);
        }
    }
}

// ---------------- launch ----------------
extern "C" void kernel_launch(void* const* d_in, const int* in_sizes, int n_in,
                              void* d_out, int out_size) {
    const float* x  = (const float*)d_in[0];
    const float* Wq = (const float*)d_in[1];
    const float* Wk = (const float*)d_in[2];
    const float* Wv = (const float*)d_in[3];
    const float* Wo = (const float*)d_in[4];
    float* out = (float*)d_out;

    __half *qkv, *att, *xh, *wc, *wo;
    cudaGetSymbolAddress((void**)&qkv, g_qkv);
    cudaGetSymbolAddress((void**)&att, g_att);
    cudaGetSymbolAddress((void**)&xh, g_xh);
    cudaGetSymbolAddress((void**)&wc, g_wc);
    cudaGetSymbolAddress((void**)&wo, g_wo);

    prep_all<<<18944, 256>>>(x, Wq, Wk, Wv, Wo, xh, wc, wo);

    const int GSM = 3 * (ASTGH + BSTGH) * 2;   // 107520
    cudaFuncSetAttribute(gemm_qkv, cudaFuncAttributeMaxDynamicSharedMemorySize, GSM);
    cudaFuncSetAttribute(gemm_out, cudaFuncAttributeMaxDynamicSharedMemorySize, GSM);

    // QKV projection + rope epilogue (256-thread variant)
    gemm_qkv<<<dim3(QKVD / GBN, M_ROWS / GBM), 256, GSM>>>(xh, wc, qkv, M_ROWS, QKVD, D_MODEL);

    // attention
    {
        const int ASM_ = (BQ * QSTH + 2 * KBUFH + 2 * VBUFH) * 2;   // 104448
        cudaFuncSetAttribute(attn_h, cudaFuncAttributeMaxDynamicSharedMemorySize, ASM_);
        attn_h<<<dim3(T_SEQ / BQ, N_HEADS, B_SZ), ATHREADS, ASM_>>>(qkv, att);
    }

    // output projection (128-thread variant)
    gemm_out<<<dim3(D_MODEL / GBN, M_ROWS / GBM), 128, GSM>>>(att, wo, out, M_ROWS, D_MODEL, QDIM);
}